// round 1
// baseline (speedup 1.0000x reference)
#include <cuda_runtime.h>

#define N_NODES 100000
#define N_EDGES 1000000
#define D_FEAT  64
#define OUT_W   (2 * D_FEAT)   // 128 floats per output row

// Scratch: per-node in-degree counts (device global — no allocation allowed).
__device__ int g_count[N_NODES];

// ---------------------------------------------------------------------------
// Kernel 1: zero the output accumulator and the counts.
// out is poisoned to 0xAA by the harness; we must zero the first half (the
// accumulator). We zero the whole thing for simplicity (second half is
// overwritten by finalize anyway).
// ---------------------------------------------------------------------------
__global__ void zero_kernel(float4* __restrict__ out4, int n_out4) {
    int i = blockIdx.x * blockDim.x + threadIdx.x;
    if (i < n_out4) out4[i] = make_float4(0.f, 0.f, 0.f, 0.f);
    if (i < N_NODES) g_count[i] = 0;
}

// ---------------------------------------------------------------------------
// Kernel 2: scatter. 16 lanes per edge. Each lane gathers one float4 of
// x[row] (half-warp reads 256B contiguous -> 2 L2 lines) and issues one
// red.global.add.v4.f32 into out[col][lane*4 .. lane*4+3].
// Lane 0 also bumps the in-degree count (no-return RED).
// ---------------------------------------------------------------------------
__global__ void scatter_kernel(const float* __restrict__ x,
                               const int*   __restrict__ es,
                               float*       __restrict__ out) {
    int t = blockIdx.x * blockDim.x + threadIdx.x;
    int e    = t >> 4;
    int lane = t & 15;
    if (e >= N_EDGES) return;

    int col = __ldg(es + e);            // es[0][e]
    int row = __ldg(es + N_EDGES + e);  // es[1][e]

    const float4 v = *reinterpret_cast<const float4*>(x + (size_t)row * D_FEAT + lane * 4);

    float* dst = out + (size_t)col * OUT_W + lane * 4;   // 16B aligned
    asm volatile("red.global.add.v4.f32 [%0], {%1, %2, %3, %4};"
                 :: "l"(dst), "f"(v.x), "f"(v.y), "f"(v.z), "f"(v.w)
                 : "memory");

    if (lane == 0) {
        asm volatile("red.global.add.s32 [%0], 1;"
                     :: "l"(&g_count[col]) : "memory");
    }
}

// ---------------------------------------------------------------------------
// Kernel 3: finalize. 16 threads per node. First half: divide accumulator by
// max(count,1). Second half: out[n, D:] = (count>0) ? x[n] : 0 — this is the
// closed form of segment_sum(x[col])/max(count,1), no scatter needed.
// ---------------------------------------------------------------------------
__global__ void finalize_kernel(const float* __restrict__ x,
                                float*       __restrict__ out) {
    int t = blockIdx.x * blockDim.x + threadIdx.x;
    if (t >= N_NODES * 16) return;
    int n = t >> 4;
    int j = t & 15;

    int c = g_count[n];
    float inv = 1.0f / (float)(c > 1 ? c : 1);

    float4* orow = reinterpret_cast<float4*>(out + (size_t)n * OUT_W);

    float4 s = orow[j];
    s.x *= inv; s.y *= inv; s.z *= inv; s.w *= inv;
    orow[j] = s;

    float4 o2 = make_float4(0.f, 0.f, 0.f, 0.f);
    if (c > 0) {
        o2 = *reinterpret_cast<const float4*>(x + (size_t)n * D_FEAT + j * 4);
    }
    orow[16 + j] = o2;
}

// ---------------------------------------------------------------------------
extern "C" void kernel_launch(void* const* d_in, const int* in_sizes, int n_in,
                              void* d_out, int out_size) {
    const float* x  = (const float*)d_in[0];   // [N_NODES, D_FEAT] fp32
    const int*   es = (const int*)d_in[1];     // [2, N_EDGES] int32
    float*       out = (float*)d_out;          // [N_NODES, 2*D_FEAT] fp32

    const int n_out4 = N_NODES * OUT_W / 4;    // 3.2M float4
    zero_kernel<<<(n_out4 + 255) / 256, 256>>>(reinterpret_cast<float4*>(out), n_out4);

    const int scatter_threads = N_EDGES * 16;  // 16M
    scatter_kernel<<<(scatter_threads + 255) / 256, 256>>>(x, es, out);

    const int fin_threads = N_NODES * 16;      // 1.6M
    finalize_kernel<<<(fin_threads + 255) / 256, 256>>>(x, out);
}